// round 17
// baseline (speedup 1.0000x reference)
#include <cuda_runtime.h>
#include <cuda_fp16.h>
#include <cstdint>

// MTLSTM: B=128, T=512, K=12, H=256, OUT=1
// Persistent kernel: 128 CTAs x 512 threads (16 warps = 4/SMSP), fp16 mma.
// 4-way batch split: CTA = (row-quarter qb of 32 rows) x (o-slice of 8 ch).
// Exchange: per-quarter release counter; two pollers (warp0->h, warp4->c) each
// issuing ONE 16KB bulk TMA to its own mbarrier; one mbar_wait per warp.
// MMA: 1 ntile/warp, double-buffered LDS.128 fragment loads.

#define NB 128
#define NT 512
#define NKF 12
#define GRID 128
#define THREADS 512

// State layout (halves): buf:65536, s(h=0,c=1):32768, qb:8192,
// ch:512, mt:256, gq:32, tq:8, hi:4, rlo:2, lo:1
__device__ __half g_S[2 * 65536];
__device__ float g_dec[NB * NT * NKF];   // (1/ln(e+dt) - 1)
__device__ unsigned g_q[4][32];          // per-quarter step counters (own lines)
__device__ unsigned g_bar0;              // init barrier

// ---------------- PTX helpers ----------------
__device__ __forceinline__ uint32_t smem_u32(const void* p) {
    return (uint32_t)__cvta_generic_to_shared(p);
}
__device__ __forceinline__ void mbar_init(uint32_t a, uint32_t cnt) {
    asm volatile("mbarrier.init.shared.b64 [%0], %1;" :: "r"(a), "r"(cnt) : "memory");
}
__device__ __forceinline__ void mbar_expect_tx(uint32_t a, uint32_t bytes) {
    asm volatile("mbarrier.arrive.expect_tx.shared.b64 _, [%0], %1;"
                 :: "r"(a), "r"(bytes) : "memory");
}
__device__ __forceinline__ void mbar_wait(uint32_t a, uint32_t parity) {
    asm volatile(
        "{\n\t.reg .pred P;\n\t"
        "W%=: mbarrier.try_wait.parity.acquire.cta.shared::cta.b64 P, [%0], %1, 0x989680;\n\t"
        "@P bra D%=;\n\t"
        "bra W%=;\n\t"
        "D%=:\n\t}"
        :: "r"(a), "r"(parity) : "memory");
}
__device__ __forceinline__ void bulk_g2s(uint32_t dst, const void* src,
                                         uint32_t bytes, uint32_t mbar) {
    asm volatile(
        "cp.async.bulk.shared::cluster.global.mbarrier::complete_tx::bytes "
        "[%0], [%1], %2, [%3];"
        :: "r"(dst), "l"(src), "r"(bytes), "r"(mbar) : "memory");
}
__device__ __forceinline__ unsigned ld_acq(const unsigned* p) {
    unsigned v;
    asm volatile("ld.acquire.gpu.global.u32 %0, [%1];" : "=r"(v) : "l"(p) : "memory");
    return v;
}
__device__ __forceinline__ void red_release_add(unsigned* p, unsigned v) {
    asm volatile("red.release.gpu.global.add.u32 [%0], %1;" :: "l"(p), "r"(v) : "memory");
}
__device__ __forceinline__ void mma_f16(float acc[4],
                                        uint32_t a0, uint32_t a1, uint32_t a2, uint32_t a3,
                                        uint32_t b0, uint32_t b1) {
    asm volatile(
        "mma.sync.aligned.m16n8k16.row.col.f32.f16.f16.f32 "
        "{%0,%1,%2,%3}, {%4,%5,%6,%7}, {%8,%9}, {%0,%1,%2,%3};\n"
        : "+f"(acc[0]), "+f"(acc[1]), "+f"(acc[2]), "+f"(acc[3])
        : "r"(a0), "r"(a1), "r"(a2), "r"(a3), "r"(b0), "r"(b1));
}
__device__ __forceinline__ float tanha(float x) {
    float r;
    asm("tanh.approx.f32 %0, %1;" : "=f"(r) : "f"(x));
    return r;
}
__device__ __forceinline__ float siga(float x) {
    return fmaf(tanha(0.5f * x), 0.5f, 0.5f);
}

// ---- smem byte layout ----
#define SM_MBAR   0                      // 2 mbarriers (h at +0, c at +8)
#define SM_A      128                    // 32768B staged state (h 16KB, c 16KB)
#define SM_CSM    (SM_A + 32768)         // 32 x 130 floats
#define SM_WIH    (SM_CSM + 32 * 130 * 4)
#define SM_BIAS   (SM_WIH + 384 * 4)
#define SM_BDE    (SM_BIAS + 32 * 4)
#define SM_TOTAL  (SM_BDE + 96 * 4)

__global__ void __launch_bounds__(THREADS, 1)
mtlstm_persistent(const float* __restrict__ xd, const float* __restrict__ dtp,
                  const float* __restrict__ Wih, const float* __restrict__ Whh,
                  const float* __restrict__ bias, const float* __restrict__ Wd,
                  const float* __restrict__ bde, const float* __restrict__ lw,
                  const float* __restrict__ lb, float* __restrict__ out) {
    extern __shared__ unsigned char smraw[];
    const __half* sA = reinterpret_cast<const __half*>(smraw + SM_A);
    float* Csm = reinterpret_cast<float*>(smraw + SM_CSM);
    float* sWih = reinterpret_cast<float*>(smraw + SM_WIH);
    float* sBias = reinterpret_cast<float*>(smraw + SM_BIAS);
    float* sBde = reinterpret_cast<float*>(smraw + SM_BDE);
    const uint32_t smbase = smem_u32(smraw);

    const int tid = threadIdx.x;
    const int qb = blockIdx.x & 3;       // row quarter: rows [qb*32, qb*32+32)
    const int oq = blockIdx.x >> 2;      // o-slice (0..31)
    const int o0 = oq * 8;               // 8 hidden channels per CTA

    if (tid == 0) {
        mbar_init(smbase + SM_MBAR, 1);       // h
        mbar_init(smbase + SM_MBAR + 8, 1);   // c
    }

    // ---- small tables ----
    if (tid < 32) {
        int g = tid >> 3, ol = tid & 7;
        sBias[tid] = bias[g * 256 + o0 + ol];
        for (int k = 0; k < NKF; ++k)
            sWih[tid * NKF + k] = Wih[(g * 256 + o0 + ol) * NKF + k];
    }
    if (tid < 96) {
        int kf = tid >> 3, ol = tid & 7;
        sBde[tid] = bde[kf * 256 + o0 + ol];
    }

    // ---- precompute decay-1 (once, cooperatively) ----
    {
        const int gt = blockIdx.x * THREADS + tid;
        const int total = NB * NT * NKF;
        for (int i = gt; i < total; i += GRID * THREADS) {
            float v = dtp[i];
            g_dec[i] = 1.0f / __logf(2.71828182845904523536f + v) - 1.0f;
        }
    }

    // ---- warp / lane mapping ----
    const int w = tid >> 5;        // 0..15, warp w owns ntile w
    const int lane = tid & 31;
    const int gq = lane >> 2;
    const int tq = lane & 3;
    // ntiles 0-3 -> gate cols (A=h), 4-15 -> decomp cols (A=c)
    const int s_w = (w < 4) ? 0 : 1;

    // ---- B weight fragments into registers (once) ----
    uint32_t breg[32];             // [ch(16)][2]
    {
        const int ncol = w * 8 + gq;   // 0..127
        const float* row;
        if (ncol < 32) {
            int g = ncol >> 3, ol = ncol & 7;
            row = Whh + (size_t)(g * 256 + o0 + ol) * 256;
        } else {
            int idx = ncol - 32;
            int kf = idx >> 3, ol = idx & 7;
            row = Wd + (size_t)(kf * 256 + o0 + ol) * 256;
        }
#pragma unroll
        for (int ch = 0; ch < 16; ++ch) {
            const int c0 = ch * 16 + 2 * tq;
            __half2 p0 = __floats2half2_rn(row[c0], row[c0 + 1]);
            __half2 p1 = __floats2half2_rn(row[c0 + 8], row[c0 + 9]);
            breg[ch * 2]     = *reinterpret_cast<uint32_t*>(&p0);
            breg[ch * 2 + 1] = *reinterpret_cast<uint32_t*>(&p1);
        }
    }

    // per-warp A base in staged smem (halves): s:8192, ch:512, mt:256
    const __half* awarp = sA + s_w * 8192 + gq * 32 + tq * 8;
    const uint32_t my_mbar = smbase + SM_MBAR + 8 * s_w;

    // ---- epilogue mapping (threads 0..255): thread -> (row eb, o eol) ----
    const int eb = (tid >> 3) & 31;      // 0..31
    const int eol = tid & 7;             // 0..7
    const int gb = qb * 32 + eb;         // global batch row
    const int go = o0 + eol;             // global hidden channel
    const int woff = qb * 8192 + (go >> 4) * 512 + ((eb >> 4) & 1) * 256 +
                     (eb & 7) * 32 + (((go & 15) >> 1) & 3) * 8 +
                     ((go & 15) >> 3) * 4 + ((eb >> 3) & 1) * 2 + (go & 1);
    const bool epi = (tid < 256);
    const float* xrow_base = xd + (size_t)gb * NT * NKF;
    const float* dec_base = g_dec + (size_t)gb * NT * NKF;
    float c_reg = 0.0f;

    unsigned* barq = &g_q[qb][0];

    // ---- init barrier: g_dec, tables, mbarriers visible ----
    __threadfence();
    __syncthreads();
    if (tid == 0) {
        atomicAdd(&g_bar0, 1u);
        while (*(volatile unsigned*)&g_bar0 < (unsigned)GRID) { }
        __threadfence();
    }
    __syncthreads();

    for (int t = 0; t < NT; ++t) {
        const int p = t & 1;       // read buffer p, write 1-p

        // ---- prefetch x, dec + hoisted x-part of gates (threads 0..255) ----
        float preX[4], d[12];
        if (epi) {
            const float* xrow = xrow_base + (size_t)t * NKF;
            const float* drow = dec_base + (size_t)t * NKF;
            float x[12];
            float4 x0 = reinterpret_cast<const float4*>(xrow)[0];
            float4 x1 = reinterpret_cast<const float4*>(xrow)[1];
            float4 x2 = reinterpret_cast<const float4*>(xrow)[2];
            x[0] = x0.x; x[1] = x0.y; x[2] = x0.z; x[3] = x0.w;
            x[4] = x1.x; x[5] = x1.y; x[6] = x1.z; x[7] = x1.w;
            x[8] = x2.x; x[9] = x2.y; x[10] = x2.z; x[11] = x2.w;
            float4 d0 = reinterpret_cast<const float4*>(drow)[0];
            float4 d1 = reinterpret_cast<const float4*>(drow)[1];
            float4 d2 = reinterpret_cast<const float4*>(drow)[2];
            d[0] = d0.x; d[1] = d0.y; d[2] = d0.z; d[3] = d0.w;
            d[4] = d1.x; d[5] = d1.y; d[6] = d1.z; d[7] = d1.w;
            d[8] = d2.x; d[9] = d2.y; d[10] = d2.z; d[11] = d2.w;
#pragma unroll
            for (int g = 0; g < 4; ++g) {
                float s = sBias[g * 8 + eol];
                const float* wr = &sWih[(g * 8 + eol) * NKF];
#pragma unroll
                for (int k = 0; k < NKF; ++k) s += x[k] * wr[k];
                preX[g] = s;
            }
        }

        float acc[2][4];
#pragma unroll
        for (int b = 0; b < 2; ++b)
#pragma unroll
            for (int c = 0; c < 4; ++c) acc[b][c] = 0.0f;

        if (t > 0) {
            // two parallel pollers: warp0-lane0 -> h bulk; warp4-lane0 -> c bulk
            if ((tid == 0) | (tid == 128)) {
                const unsigned target = (unsigned)t * 32u;
                while (ld_acq(barq) < target) { }
                const __half* gsrc = g_S + (size_t)p * 65536 + qb * 8192;
                const int s = (tid == 0) ? 0 : 1;
                uint32_t mb = smbase + SM_MBAR + 8 * s;
                mbar_expect_tx(mb, 16384);
                bulk_g2s(smbase + SM_A + s * 16384,
                         gsrc + s * 32768, 16384, mb);
            }
            const uint32_t par = (uint32_t)((t - 1) & 1);
            mbar_wait(my_mbar, par);

            // double-buffered fragment loads: 32 LDS.128 + 32 HMMA per warp
            uint4 va = *reinterpret_cast<const uint4*>(awarp);
            uint4 vb = *reinterpret_cast<const uint4*>(awarp + 256);
#pragma unroll
            for (int ch = 0; ch < 16; ++ch) {
                uint4 na, nb;
                if (ch < 15) {
                    na = *reinterpret_cast<const uint4*>(awarp + (ch + 1) * 512);
                    nb = *reinterpret_cast<const uint4*>(awarp + (ch + 1) * 512 + 256);
                }
                mma_f16(acc[0], va.x, va.y, va.z, va.w,
                        breg[ch * 2], breg[ch * 2 + 1]);
                mma_f16(acc[1], vb.x, vb.y, vb.z, vb.w,
                        breg[ch * 2], breg[ch * 2 + 1]);
                va = na; vb = nb;
            }
        }

        // ---- dump accumulators to Csm (32 rows x 130 cols) ----
        {
            const int col0 = w * 8 + 2 * tq;
#pragma unroll
            for (int mt = 0; mt < 2; ++mt) {
                const int rr = mt * 16 + gq;
                *reinterpret_cast<float2*>(&Csm[rr * 130 + col0]) =
                    make_float2(acc[mt][0], acc[mt][1]);
                *reinterpret_cast<float2*>(&Csm[(rr + 8) * 130 + col0]) =
                    make_float2(acc[mt][2], acc[mt][3]);
            }
        }
        __syncthreads();

        // ---- epilogue (threads 0..255) ----
        if (epi) {
            float ig = siga(preX[0] + Csm[eb * 130 + 0 + eol]);
            float fg = siga(preX[1] + Csm[eb * 130 + 8 + eol]);
            float gg = tanha(preX[2] + Csm[eb * 130 + 16 + eol]);
            float og = siga(preX[3] + Csm[eb * 130 + 24 + eol]);

            float S = 0.0f;
#pragma unroll
            for (int k = 0; k < NKF; ++k) {
                float cs = tanha(Csm[eb * 130 + 32 + k * 8 + eol] + sBde[k * 8 + eol]);
                S += cs * d[k];
            }

            float cn = fg * (c_reg + S) + ig * gg;
            c_reg = cn;
            float hn = og * tanha(cn);
            __half* gdst = g_S + (size_t)(1 - p) * 65536 + woff;
            gdst[0] = __float2half_rn(hn);        // s=0 (h)
            gdst[32768] = __float2half_rn(cn);    // s=1 (c)
        }

        // ---- publish: CTA-wide sync, then single release-arrive ----
        __syncthreads();
        if (tid == 0) red_release_add(barq, 1u);
    }

    // ---- final: wait for the quarter containing output row b = blockIdx.x ----
    {
        const int omq = blockIdx.x >> 5;     // quarter of output row
        if (tid == 0) {
            const unsigned tgt = (unsigned)NT * 32u;
            while (ld_acq(&g_q[omq][0]) < tgt) { }
        }
        __syncthreads();

        if (w == 0) {
            const int b = blockIdx.x;
            const int r = b & 31;
            const int rpart = omq * 8192 + ((r >> 4) & 1) * 256 + (r & 7) * 32 +
                              ((r >> 3) & 1) * 2;
            float ssum = 0.0f;
            for (int dd = lane; dd < 256; dd += 32) {
                const int kk = dd & 15;
                const int off = rpart + (dd >> 4) * 512 + ((kk >> 1) & 3) * 8 +
                                (kk >> 3) * 4 + (kk & 1);
                ssum += __half2float(g_S[off]) * lw[dd];   // buf 0 (step 511), s=0
            }
#pragma unroll
            for (int off = 16; off; off >>= 1)
                ssum += __shfl_xor_sync(0xffffffffu, ssum, off);
            if (lane == 0) out[b] = ssum + lb[0];
        }
    }
}

__global__ void mtlstm_barzero() {
    g_bar0 = 0u;
    for (int q = 0; q < 4; ++q) g_q[q][0] = 0u;
}

extern "C" void kernel_launch(void* const* d_in, const int* in_sizes, int n_in,
                              void* d_out, int out_size) {
    const float* xd  = (const float*)d_in[0];
    const float* dtp = (const float*)d_in[1];
    const float* wih = (const float*)d_in[2];
    const float* whh = (const float*)d_in[3];
    const float* bia = (const float*)d_in[4];
    const float* wd  = (const float*)d_in[5];
    const float* bde = (const float*)d_in[6];
    const float* lw  = (const float*)d_in[7];
    const float* lb  = (const float*)d_in[8];
    float* out = (float*)d_out;

    cudaFuncSetAttribute(mtlstm_persistent,
                         cudaFuncAttributeMaxDynamicSharedMemorySize, SM_TOTAL);

    mtlstm_barzero<<<1, 1>>>();
    mtlstm_persistent<<<GRID, THREADS, SM_TOTAL>>>(xd, dtp, wih, whh, bia, wd,
                                                   bde, lw, lb, out);
}